// round 3
// baseline (speedup 1.0000x reference)
#include <cuda_runtime.h>
#include <mma.h>
#include <math.h>

using namespace nvcuda;

// ---------------- static problem dims ----------------
#define BB    32
#define HH    56
#define WWD   56
#define CC    384
#define NTOK  (BB * HH * WWD)      // 100352
#define LL    49
#define NWIN  2048
#define C3    1152
#define NHEAD 12
#define HDIM  32

// ---------------- scratch (device globals; no allocs allowed) ----------------
__device__ float g_yw[(size_t)NTOK * CC];    // layernormed, window-ordered
__device__ float g_qkv[(size_t)NTOK * C3];   // qkv projection, window-ordered
__device__ float g_att[(size_t)NTOK * CC];   // attention output, window-ordered

// ---------------- K1: LayerNorm + window partition ----------------
__global__ void ln_window_kernel(const float* __restrict__ x,
                                 const float* __restrict__ gamma,
                                 const float* __restrict__ beta) {
    int t = blockIdx.x;                 // token in original order
    int tid = threadIdx.x;              // 128 threads
    const float* xin = x + (size_t)t * CC;
    float v0 = xin[tid], v1 = xin[tid + 128], v2 = xin[tid + 256];
    float s = v0 + v1 + v2;
    float s2 = v0 * v0 + v1 * v1 + v2 * v2;
    #pragma unroll
    for (int o = 16; o; o >>= 1) {
        s  += __shfl_down_sync(0xffffffffu, s, o);
        s2 += __shfl_down_sync(0xffffffffu, s2, o);
    }
    __shared__ float red[2][4];
    int wid = tid >> 5, lane = tid & 31;
    if (lane == 0) { red[0][wid] = s; red[1][wid] = s2; }
    __syncthreads();
    if (tid == 0) {
        float a = red[0][0] + red[0][1] + red[0][2] + red[0][3];
        float b = red[1][0] + red[1][1] + red[1][2] + red[1][3];
        float mu = a * (1.0f / CC);
        float var = b * (1.0f / CC) - mu * mu;
        red[0][0] = mu;
        red[1][0] = rsqrtf(var + 1e-5f);
    }
    __syncthreads();
    float mu = red[0][0], rs = red[1][0];

    // window-ordered destination row
    int b_ = t / (HH * WWD);
    int n  = t % (HH * WWD);
    int h = n / WWD, w = n % WWD;
    int wi = h / 7, i = h % 7, wj = w / 7, j = w % 7;
    int row = (b_ * 64 + wi * 8 + wj) * LL + i * 7 + j;
    float* out = g_yw + (size_t)row * CC;
    out[tid]       = (v0 - mu) * rs * gamma[tid]       + beta[tid];
    out[tid + 128] = (v1 - mu) * rs * gamma[tid + 128] + beta[tid + 128];
    out[tid + 256] = (v2 - mu) * rs * gamma[tid + 256] + beta[tid + 256];
}

// ---------------- K2/K4: TF32 wmma GEMM  C[m,n] = A[m,:] . Bw[n,:] + bias ----------------
// EPI==0: A = g_yw,  write g_qkv, plain + bias
// EPI==1: A = g_att, write d_out with window-reverse + residual + bias
template <int EPI>
__global__ void gemm_tf32_kernel(const float* __restrict__ Bw,
                                 const float* __restrict__ bias,
                                 const float* __restrict__ resid,
                                 float* __restrict__ Cout,
                                 int N, int K) {
    __shared__ float smem[5120];        // As 64x40, Bs 64x40; reused as Cs 64x64
    float* As = smem;
    float* Bs = smem + 2560;
    const float* A  = (EPI == 0) ? g_yw : g_att;
    float*       Cw = (EPI == 0) ? g_qkv : Cout;   // <-- bug fix: EPI==0 writes device global

    int tid = threadIdx.x;              // 128 threads, 4 warps
    int warp = tid >> 5;
    int wm = warp >> 1, wn = warp & 1;
    int n0 = blockIdx.x * 64;
    int m0 = blockIdx.y * 64;

    wmma::fragment<wmma::accumulator, 16, 16, 8, float> acc[2][2];
    #pragma unroll
    for (int a = 0; a < 2; a++)
        #pragma unroll
        for (int b = 0; b < 2; b++) wmma::fill_fragment(acc[a][b], 0.0f);

    for (int k0 = 0; k0 < K; k0 += 32) {
        #pragma unroll
        for (int q = 0; q < 4; q++) {
            int idx = tid + q * 128;    // 512 float4 per matrix
            int r = idx >> 3, c4 = (idx & 7) * 4;
            float4 va = *(const float4*)(A  + (size_t)(m0 + r) * K + k0 + c4);
            *(float4*)(As + r * 40 + c4) = va;
            float4 vb = *(const float4*)(Bw + (size_t)(n0 + r) * K + k0 + c4);
            *(float4*)(Bs + r * 40 + c4) = vb;
        }
        __syncthreads();
        #pragma unroll
        for (int kk = 0; kk < 32; kk += 8) {
            wmma::fragment<wmma::matrix_a, 16, 16, 8, wmma::precision::tf32, wmma::row_major> af[2];
            wmma::fragment<wmma::matrix_b, 16, 16, 8, wmma::precision::tf32, wmma::col_major> bf[2];
            #pragma unroll
            for (int mi = 0; mi < 2; mi++) {
                wmma::load_matrix_sync(af[mi], As + (wm * 32 + mi * 16) * 40 + kk, 40);
                #pragma unroll
                for (int e = 0; e < af[mi].num_elements; e++)
                    af[mi].x[e] = wmma::__float_to_tf32(af[mi].x[e]);
            }
            #pragma unroll
            for (int ni = 0; ni < 2; ni++) {
                wmma::load_matrix_sync(bf[ni], Bs + (wn * 32 + ni * 16) * 40 + kk, 40);
                #pragma unroll
                for (int e = 0; e < bf[ni].num_elements; e++)
                    bf[ni].x[e] = wmma::__float_to_tf32(bf[ni].x[e]);
            }
            #pragma unroll
            for (int mi = 0; mi < 2; mi++)
                #pragma unroll
                for (int ni = 0; ni < 2; ni++)
                    wmma::mma_sync(acc[mi][ni], af[mi], bf[ni], acc[mi][ni]);
        }
        __syncthreads();
    }

    // epilogue via shared staging
    float* Cs = smem;                   // 64x64
    #pragma unroll
    for (int mi = 0; mi < 2; mi++)
        #pragma unroll
        for (int ni = 0; ni < 2; ni++)
            wmma::store_matrix_sync(Cs + (wm * 32 + mi * 16) * 64 + wn * 32 + ni * 16,
                                    acc[mi][ni], 64, wmma::mem_row_major);
    __syncthreads();
    #pragma unroll
    for (int q = 0; q < 32; q++) {
        int idx = tid + q * 128;        // 4096 elements
        int r = idx >> 6, c = idx & 63;
        float val = Cs[idx] + bias[n0 + c];
        int m = m0 + r;
        if (EPI == 0) {
            Cw[(size_t)m * N + n0 + c] = val;
        } else {
            int win = m / LL, l = m % LL;
            int b_ = win >> 6, wr = win & 63;
            int wi = wr >> 3, wj = wr & 7;
            int i = l / 7, j = l % 7;
            size_t orig = (size_t)b_ * (HH * WWD) + (size_t)(wi * 7 + i) * WWD + (wj * 7 + j);
            size_t off = orig * CC + n0 + c;
            Cw[off] = resid[off] + val;
        }
    }
}

// ---------------- K3: per-(window, head) attention in fp32 ----------------
__global__ void attn_kernel() {
    __shared__ float qs[LL * 33];
    __shared__ float ks[LL * 33];
    __shared__ float vs[LL * 33];
    __shared__ float ss[LL * 50];
    int win = blockIdx.x;
    int head = blockIdx.y;
    int tid = threadIdx.x;              // 128 threads
    const float scale = 0.17677669529663687f;   // 1/sqrt(32)

    const float* base = g_qkv + (size_t)win * LL * C3 + head * HDIM;
    for (int idx = tid; idx < LL * 8; idx += 128) {
        int l = idx >> 3, d4 = (idx & 7) * 4;
        const float* p = base + (size_t)l * C3;
        float4 q4 = *(const float4*)(p + d4);
        float4 k4 = *(const float4*)(p + 384 + d4);
        float4 v4 = *(const float4*)(p + 768 + d4);
        qs[l * 33 + d4 + 0] = q4.x * scale; qs[l * 33 + d4 + 1] = q4.y * scale;
        qs[l * 33 + d4 + 2] = q4.z * scale; qs[l * 33 + d4 + 3] = q4.w * scale;
        ks[l * 33 + d4 + 0] = k4.x; ks[l * 33 + d4 + 1] = k4.y;
        ks[l * 33 + d4 + 2] = k4.z; ks[l * 33 + d4 + 3] = k4.w;
        vs[l * 33 + d4 + 0] = v4.x; vs[l * 33 + d4 + 1] = v4.y;
        vs[l * 33 + d4 + 2] = v4.z; vs[l * 33 + d4 + 3] = v4.w;
    }
    __syncthreads();

    int warp = tid >> 5, lane = tid & 31;
    bool has2 = lane < 17;              // second column j = lane+32 < 49
    int j2 = has2 ? (lane + 32) : 48;   // clamp (result discarded if !has2)

    // scores: warp per query row; lane -> key columns {lane, lane+32}
    for (int i = warp; i < LL; i += 4) {
        const float* qr = qs + i * 33;
        const float* k0p = ks + lane * 33;
        const float* k1p = ks + j2 * 33;
        float s0 = 0.f, s1 = 0.f;
        #pragma unroll
        for (int d = 0; d < HDIM; d++) {
            float qv = qr[d];           // broadcast across lanes
            s0 += qv * k0p[d];
            s1 += qv * k1p[d];
        }
        ss[i * 50 + lane] = s0;
        if (has2) ss[i * 50 + lane + 32] = s1;
    }
    __syncthreads();

    // softmax per row
    for (int i = warp; i < LL; i += 4) {
        float a = ss[i * 50 + lane];
        float b = has2 ? ss[i * 50 + lane + 32] : -3.0e38f;
        float m = fmaxf(a, b);
        #pragma unroll
        for (int o = 16; o; o >>= 1) m = fmaxf(m, __shfl_xor_sync(0xffffffffu, m, o));
        float e0 = __expf(a - m);
        float e1 = has2 ? __expf(b - m) : 0.f;
        float sm = e0 + e1;
        #pragma unroll
        for (int o = 16; o; o >>= 1) sm += __shfl_xor_sync(0xffffffffu, sm, o);
        float inv = 1.0f / sm;
        ss[i * 50 + lane] = e0 * inv;
        if (has2) ss[i * 50 + lane + 32] = e1 * inv;
    }
    __syncthreads();

    // O = P @ V: warp per row; lane -> head dim d
    for (int i = warp; i < LL; i += 4) {
        const float* pr = ss + i * 50;  // broadcast across lanes
        float o = 0.f;
        #pragma unroll
        for (int j = 0; j < LL; j++) o += pr[j] * vs[j * 33 + lane];
        g_att[((size_t)win * LL + i) * CC + head * HDIM + lane] = o;
    }
}

// ---------------- launch ----------------
extern "C" void kernel_launch(void* const* d_in, const int* in_sizes, int n_in,
                              void* d_out, int out_size) {
    const float* x     = (const float*)d_in[0];
    const float* gamma = (const float*)d_in[1];
    const float* beta  = (const float*)d_in[2];
    const float* w_in  = (const float*)d_in[3];
    const float* b_in  = (const float*)d_in[4];
    const float* w_out = (const float*)d_in[5];
    const float* b_out = (const float*)d_in[6];
    float* out = (float*)d_out;

    ln_window_kernel<<<NTOK, 128>>>(x, gamma, beta);
    gemm_tf32_kernel<0><<<dim3(C3 / 64, NTOK / 64), 128>>>(w_in, b_in, nullptr, nullptr, C3, CC);
    attn_kernel<<<dim3(NWIN, NHEAD), 128>>>();
    gemm_tf32_kernel<1><<<dim3(CC / 64, NTOK / 64), 128>>>(w_out, b_out, x, out, CC, CC);
}

// round 4
// speedup vs baseline: 1.0957x; 1.0957x over previous
#include <cuda_runtime.h>
#include <mma.h>
#include <math.h>

using namespace nvcuda;

// ---------------- static problem dims ----------------
#define BB    32
#define HH    56
#define WWD   56
#define CC    384
#define NTOK  (BB * HH * WWD)      // 100352
#define LL    49
#define NWIN  2048
#define C3    1152
#define NHEAD 12
#define HDIM  32

// ---------------- scratch (device globals; no allocs allowed) ----------------
__device__ float g_yw[(size_t)NTOK * CC];    // layernormed, window-ordered
__device__ float g_qkv[(size_t)NTOK * C3];   // qkv projection, window-ordered
__device__ float g_att[(size_t)NTOK * CC];   // attention output, window-ordered

// ---------------- K1: LayerNorm + window partition ----------------
__global__ void ln_window_kernel(const float* __restrict__ x,
                                 const float* __restrict__ gamma,
                                 const float* __restrict__ beta) {
    int t = blockIdx.x;                 // token in original order
    int tid = threadIdx.x;              // 128 threads
    const float* xin = x + (size_t)t * CC;
    float v0 = xin[tid], v1 = xin[tid + 128], v2 = xin[tid + 256];
    float s = v0 + v1 + v2;
    float s2 = v0 * v0 + v1 * v1 + v2 * v2;
    #pragma unroll
    for (int o = 16; o; o >>= 1) {
        s  += __shfl_down_sync(0xffffffffu, s, o);
        s2 += __shfl_down_sync(0xffffffffu, s2, o);
    }
    __shared__ float red[2][4];
    int wid = tid >> 5, lane = tid & 31;
    if (lane == 0) { red[0][wid] = s; red[1][wid] = s2; }
    __syncthreads();
    if (tid == 0) {
        float a = red[0][0] + red[0][1] + red[0][2] + red[0][3];
        float b = red[1][0] + red[1][1] + red[1][2] + red[1][3];
        float mu = a * (1.0f / CC);
        float var = b * (1.0f / CC) - mu * mu;
        red[0][0] = mu;
        red[1][0] = rsqrtf(var + 1e-5f);
    }
    __syncthreads();
    float mu = red[0][0], rs = red[1][0];

    int b_ = t / (HH * WWD);
    int n  = t % (HH * WWD);
    int h = n / WWD, w = n % WWD;
    int wi = h / 7, i = h % 7, wj = w / 7, j = w % 7;
    int row = (b_ * 64 + wi * 8 + wj) * LL + i * 7 + j;
    float* out = g_yw + (size_t)row * CC;
    out[tid]       = (v0 - mu) * rs * gamma[tid]       + beta[tid];
    out[tid + 128] = (v1 - mu) * rs * gamma[tid + 128] + beta[tid + 128];
    out[tid + 256] = (v2 - mu) * rs * gamma[tid + 256] + beta[tid + 256];
}

// ---------------- K2/K4: TF32 wmma GEMM, 128x64 block tile, 64x32 warp tile ----
// EPI==0: A = g_yw,  write g_qkv, plain + bias
// EPI==1: A = g_att, write d_out with window-reverse + residual + bias
// tf32 conversion is done ONCE at smem fill; fragments load pre-converted data.
template <int EPI>
__global__ void __launch_bounds__(128) gemm_tf32_kernel(
        const float* __restrict__ Bw,
        const float* __restrict__ bias,
        const float* __restrict__ resid,
        float* __restrict__ Cout,
        int N, int K) {
    __shared__ float smem[8192];        // As 128x40 (5120) + Bs 64x40 (2560); Cs 128x64
    float* As = smem;
    float* Bs = smem + 5120;
    const float* A  = (EPI == 0) ? g_yw : g_att;
    float*       Cw = (EPI == 0) ? g_qkv : Cout;

    int tid = threadIdx.x;              // 128 threads, 4 warps
    int warp = tid >> 5;
    int wm = warp >> 1, wn = warp & 1;  // warp covers rows wm*64..+64, cols wn*32..+32
    int n0 = blockIdx.x * 64;
    int m0 = blockIdx.y * 128;

    wmma::fragment<wmma::accumulator, 16, 16, 8, float> acc[4][2];
    #pragma unroll
    for (int a = 0; a < 4; a++)
        #pragma unroll
        for (int b = 0; b < 2; b++) wmma::fill_fragment(acc[a][b], 0.0f);

    for (int k0 = 0; k0 < K; k0 += 32) {
        // fill A tile: 128x32 = 1024 float4, 8 per thread (convert to tf32 here)
        #pragma unroll
        for (int q = 0; q < 8; q++) {
            int idx = tid + q * 128;
            int r = idx >> 3, c4 = (idx & 7) * 4;
            float4 v = *(const float4*)(A + (size_t)(m0 + r) * K + k0 + c4);
            float* d = As + r * 40 + c4;
            d[0] = wmma::__float_to_tf32(v.x);
            d[1] = wmma::__float_to_tf32(v.y);
            d[2] = wmma::__float_to_tf32(v.z);
            d[3] = wmma::__float_to_tf32(v.w);
        }
        // fill B tile: 64x32 = 512 float4, 4 per thread
        #pragma unroll
        for (int q = 0; q < 4; q++) {
            int idx = tid + q * 128;
            int r = idx >> 3, c4 = (idx & 7) * 4;
            float4 v = *(const float4*)(Bw + (size_t)(n0 + r) * K + k0 + c4);
            float* d = Bs + r * 40 + c4;
            d[0] = wmma::__float_to_tf32(v.x);
            d[1] = wmma::__float_to_tf32(v.y);
            d[2] = wmma::__float_to_tf32(v.z);
            d[3] = wmma::__float_to_tf32(v.w);
        }
        __syncthreads();
        #pragma unroll
        for (int kk = 0; kk < 32; kk += 8) {
            wmma::fragment<wmma::matrix_a, 16, 16, 8, wmma::precision::tf32, wmma::row_major> af[4];
            wmma::fragment<wmma::matrix_b, 16, 16, 8, wmma::precision::tf32, wmma::col_major> bf[2];
            #pragma unroll
            for (int mi = 0; mi < 4; mi++)
                wmma::load_matrix_sync(af[mi], As + (wm * 64 + mi * 16) * 40 + kk, 40);
            #pragma unroll
            for (int ni = 0; ni < 2; ni++)
                wmma::load_matrix_sync(bf[ni], Bs + (wn * 32 + ni * 16) * 40 + kk, 40);
            #pragma unroll
            for (int mi = 0; mi < 4; mi++)
                #pragma unroll
                for (int ni = 0; ni < 2; ni++)
                    wmma::mma_sync(acc[mi][ni], af[mi], bf[ni], acc[mi][ni]);
        }
        __syncthreads();
    }

    // epilogue via shared staging (Cs 128x64 = 8192 floats)
    float* Cs = smem;
    #pragma unroll
    for (int mi = 0; mi < 4; mi++)
        #pragma unroll
        for (int ni = 0; ni < 2; ni++)
            wmma::store_matrix_sync(Cs + (wm * 64 + mi * 16) * 64 + wn * 32 + ni * 16,
                                    acc[mi][ni], 64, wmma::mem_row_major);
    __syncthreads();
    #pragma unroll
    for (int q = 0; q < 64; q++) {
        int idx = tid + q * 128;        // 8192 elements
        int r = idx >> 6, c = idx & 63;
        float val = Cs[idx] + bias[n0 + c];
        int m = m0 + r;
        if (EPI == 0) {
            Cw[(size_t)m * N + n0 + c] = val;
        } else {
            int win = m / LL, l = m % LL;
            int b_ = win >> 6, wr = win & 63;
            int wi = wr >> 3, wj = wr & 7;
            int i = l / 7, j = l % 7;
            size_t orig = (size_t)b_ * (HH * WWD) + (size_t)(wi * 7 + i) * WWD + (wj * 7 + j);
            size_t off = orig * CC + n0 + c;
            Cw[off] = resid[off] + val;
        }
    }
}

// ---------------- K3: per-(window, head) attention in fp32 ----------------
__global__ void attn_kernel() {
    __shared__ float qs[LL * 33];
    __shared__ float ks[LL * 33];
    __shared__ float vs[LL * 33];
    __shared__ float ss[LL * 50];
    int win = blockIdx.x;
    int head = blockIdx.y;
    int tid = threadIdx.x;              // 128 threads
    const float scale = 0.17677669529663687f;   // 1/sqrt(32)

    const float* base = g_qkv + (size_t)win * LL * C3 + head * HDIM;
    for (int idx = tid; idx < LL * 8; idx += 128) {
        int l = idx >> 3, d4 = (idx & 7) * 4;
        const float* p = base + (size_t)l * C3;
        float4 q4 = *(const float4*)(p + d4);
        float4 k4 = *(const float4*)(p + 384 + d4);
        float4 v4 = *(const float4*)(p + 768 + d4);
        qs[l * 33 + d4 + 0] = q4.x * scale; qs[l * 33 + d4 + 1] = q4.y * scale;
        qs[l * 33 + d4 + 2] = q4.z * scale; qs[l * 33 + d4 + 3] = q4.w * scale;
        ks[l * 33 + d4 + 0] = k4.x; ks[l * 33 + d4 + 1] = k4.y;
        ks[l * 33 + d4 + 2] = k4.z; ks[l * 33 + d4 + 3] = k4.w;
        vs[l * 33 + d4 + 0] = v4.x; vs[l * 33 + d4 + 1] = v4.y;
        vs[l * 33 + d4 + 2] = v4.z; vs[l * 33 + d4 + 3] = v4.w;
    }
    __syncthreads();

    int warp = tid >> 5, lane = tid & 31;
    bool has2 = lane < 17;
    int j2 = has2 ? (lane + 32) : 48;

    for (int i = warp; i < LL; i += 4) {
        const float* qr = qs + i * 33;
        const float* k0p = ks + lane * 33;
        const float* k1p = ks + j2 * 33;
        float s0 = 0.f, s1 = 0.f;
        #pragma unroll
        for (int d = 0; d < HDIM; d++) {
            float qv = qr[d];
            s0 += qv * k0p[d];
            s1 += qv * k1p[d];
        }
        ss[i * 50 + lane] = s0;
        if (has2) ss[i * 50 + lane + 32] = s1;
    }
    __syncthreads();

    for (int i = warp; i < LL; i += 4) {
        float a = ss[i * 50 + lane];
        float b = has2 ? ss[i * 50 + lane + 32] : -3.0e38f;
        float m = fmaxf(a, b);
        #pragma unroll
        for (int o = 16; o; o >>= 1) m = fmaxf(m, __shfl_xor_sync(0xffffffffu, m, o));
        float e0 = __expf(a - m);
        float e1 = has2 ? __expf(b - m) : 0.f;
        float sm = e0 + e1;
        #pragma unroll
        for (int o = 16; o; o >>= 1) sm += __shfl_xor_sync(0xffffffffu, sm, o);
        float inv = 1.0f / sm;
        ss[i * 50 + lane] = e0 * inv;
        if (has2) ss[i * 50 + lane + 32] = e1 * inv;
    }
    __syncthreads();

    for (int i = warp; i < LL; i += 4) {
        const float* pr = ss + i * 50;
        float o = 0.f;
        #pragma unroll
        for (int j = 0; j < LL; j++) o += pr[j] * vs[j * 33 + lane];
        g_att[((size_t)win * LL + i) * CC + head * HDIM + lane] = o;
    }
}

// ---------------- launch ----------------
extern "C" void kernel_launch(void* const* d_in, const int* in_sizes, int n_in,
                              void* d_out, int out_size) {
    const float* x     = (const float*)d_in[0];
    const float* gamma = (const float*)d_in[1];
    const float* beta  = (const float*)d_in[2];
    const float* w_in  = (const float*)d_in[3];
    const float* b_in  = (const float*)d_in[4];
    const float* w_out = (const float*)d_in[5];
    const float* b_out = (const float*)d_in[6];
    float* out = (float*)d_out;

    ln_window_kernel<<<NTOK, 128>>>(x, gamma, beta);
    gemm_tf32_kernel<0><<<dim3(C3 / 64, NTOK / 128), 128>>>(w_in, b_in, nullptr, nullptr, C3, CC);
    attn_kernel<<<dim3(NWIN, NHEAD), 128>>>();
    gemm_tf32_kernel<1><<<dim3(CC / 64, NTOK / 128), 128>>>(w_out, b_out, x, out, CC, CC);
}